// round 4
// baseline (speedup 1.0000x reference)
#include <cuda_runtime.h>
#include <cuda_bf16.h>
#include <cfloat>

#define NN 2048
#define FF 64
#define KTOP 8
#define OUT_ROW ((KTOP + 1) * FF)   // 576

#define NBINS 512
#define BIN_HI 4.25f
#define BIN_W  (8.5f / (float)NBINS)
#define BIN_INVW ((float)NBINS / 8.5f)

#define SSTAGE 1024     // pairs staged in smem per block (8 KB)
#define BATCH 8         // steps/batch; 2 streams -> 16 candidates/batch
#define MPW 16          // m-columns per warp

__device__ float2 g_binned[FF * NN];   // 1 MB scratch
__device__ float  g_xT[FF * NN];       // 512 KB transposed x

__device__ __forceinline__ int bin_of(float v) {
    int b = (int)((BIN_HI - v) * BIN_INVW);
    return max(0, min(NBINS - 1, b));
}
__device__ __forceinline__ float remaining_bound(float v) {
    int b = bin_of(v);
    return (b == 0) ? FLT_MAX : (BIN_HI - (float)b * BIN_W + 1e-3f);
}
__device__ __forceinline__ void CE(float& a, float& b) {
    float hi = fmaxf(a, b), lo = fminf(a, b); a = hi; b = lo;
}

// ---------------------------------------------------------------------------
// Kernel 0: transpose x [NN,FF] -> g_xT [FF,NN]  (coalesced both ways)
// ---------------------------------------------------------------------------
__global__ void transpose_kernel(const float* __restrict__ x) {
    __shared__ float tile[32][33];
    const int nb = blockIdx.x * 32;   // n base
    const int fb = blockIdx.y * 32;   // f base
    const int tx = threadIdx.x, ty = threadIdx.y;   // 32 x 8
#pragma unroll
    for (int r = ty; r < 32; r += 8)
        tile[r][tx] = __ldg(&x[(nb + r) * FF + fb + tx]);
    __syncthreads();
#pragma unroll
    for (int r = ty; r < 32; r += 8)
        g_xT[(size_t)(fb + r) * NN + nb + tx] = tile[tx][r];
}

// ---------------------------------------------------------------------------
// Kernel 1: per-feature bucket binning (coalesced reads from g_xT)
// ---------------------------------------------------------------------------
__global__ void __launch_bounds__(512) bin_cols_kernel() {
    __shared__ float sx[NN];
    __shared__ int   cnt[NBINS];
    __shared__ int   sa[NBINS];
    __shared__ int   sb[NBINS];
    __shared__ int   cursor[NBINS];

    const int f   = blockIdx.x;
    const int tid = threadIdx.x;
    const int bs  = blockDim.x;   // 512

    for (int i = tid; i < NBINS; i += bs) cnt[i] = 0;
    __syncthreads();

    const float4* xcol = (const float4*)(g_xT + (size_t)f * NN);
    for (int i4 = tid; i4 < NN / 4; i4 += bs) {
        float4 w = __ldg(xcol + i4);
        sx[i4 * 4 + 0] = w.x; sx[i4 * 4 + 1] = w.y;
        sx[i4 * 4 + 2] = w.z; sx[i4 * 4 + 3] = w.w;
        atomicAdd(&cnt[bin_of(w.x)], 1);
        atomicAdd(&cnt[bin_of(w.y)], 1);
        atomicAdd(&cnt[bin_of(w.z)], 1);
        atomicAdd(&cnt[bin_of(w.w)], 1);
    }
    __syncthreads();

    for (int i = tid; i < NBINS; i += bs) sa[i] = cnt[i];
    __syncthreads();
    int* src = sa; int* dst = sb;
    for (int d = 1; d < NBINS; d <<= 1) {
        for (int i = tid; i < NBINS; i += bs)
            dst[i] = src[i] + ((i >= d) ? src[i - d] : 0);
        __syncthreads();
        int* t = src; src = dst; dst = t;
    }
    for (int i = tid; i < NBINS; i += bs) cursor[i] = src[i] - cnt[i];
    __syncthreads();

    float2* out = g_binned + (size_t)f * NN;
    for (int i = tid; i < NN; i += bs) {
        float v = sx[i];
        int pos = atomicAdd(&cursor[bin_of(v)], 1);
        out[pos] = make_float2(v, __int_as_float(i));
    }
}

// ---------------------------------------------------------------------------
// Kernel 2: pruned top-8 scan, 2 candidate streams per warp (16 m/warp).
// 8192 warps total; blocks of 4 warps all share feature f.
// ---------------------------------------------------------------------------
__global__ void __launch_bounds__(128, 10) topk_scan_kernel(
        const float* __restrict__ adj,
        const float* __restrict__ x,
        float* __restrict__ out) {
    __shared__ float2 sp[SSTAGE];   // 8 KB

    const int gtid = blockIdx.x * blockDim.x + threadIdx.x;
    const int warp = gtid >> 5;
    const int lane = threadIdx.x & 31;
    const int f  = warp >> 7;          // 128 m-groups per feature
    const int mg = warp & 127;
    const int sub = lane >> 4;         // candidate-stream parity
    const int lm  = lane & 15;
    const int m   = mg * MPW + lm;

    const float2* __restrict__ pairs = g_binned + (size_t)f * NN;

    // Cooperative stage (all 4 warps of this block share f)
    {
        const float4* s4 = (const float4*)pairs;
        float4* d4 = (float4*)sp;
        for (int i = threadIdx.x; i < SSTAGE / 2; i += blockDim.x)
            d4[i] = __ldg(s4 + i);
    }
    __syncthreads();

    const float* __restrict__ acol = adj + m;

    float arr[KTOP];
#pragma unroll
    for (int j = 0; j < KTOP; j++) arr[j] = -FLT_MAX;

#define PAIR_AT(i) ((i) < SSTAGE ? sp[(i)] : __ldg(&pairs[(i)]))

    float aC[BATCH], aN[BATCH];

    // Prologue: adj loads for batch 0 (candidate i = 2*step + sub)
#pragma unroll
    for (int c = 0; c < BATCH; c++) {
        float2 p = PAIR_AT(2 * c + sub);
        aC[c] = __ldg(acol + (size_t)__float_as_int(p.y) * NN);
    }

    int base = 0;                 // step base; steps go to NN/2
    while (true) {
        const int nbase = base + BATCH;

        if (nbase < NN / 2) {     // prefetch next batch's adj (8 LDGs in flight)
#pragma unroll
            for (int c = 0; c < BATCH; c++) {
                float2 p = PAIR_AT(2 * (nbase + c) + sub);
                aN[c] = __ldg(acol + (size_t)__float_as_int(p.y) * NN);
            }
        }

        float lastx = 0.0f;
#pragma unroll
        for (int c = 0; c < BATCH; c++) {
            float2 p = PAIR_AT(2 * (base + c) + sub);
            float v = aC[c] * p.x;
            if (c == BATCH - 1) lastx = p.x;
            if (__any_sync(0xffffffffu, v > arr[KTOP - 1])) {
                float keep = v;
#pragma unroll
                for (int j = 0; j < KTOP; j++) {
                    float mx = fmaxf(arr[j], keep);
                    keep     = fminf(arr[j], keep);
                    arr[j]   = mx;
                }
            }
        }

        // Union 8th-largest >= max of the two parity 8th-largests -> safe stop
        float thr = fmaxf(arr[KTOP - 1],
                          __shfl_xor_sync(0xffffffffu, arr[KTOP - 1], 16));
        bool more = (fmaxf(remaining_bound(lastx), 0.0f) > thr);
        base = nbase;
        if (base >= NN / 2 || !__any_sync(0xffffffffu, more)) break;
#pragma unroll
        for (int c = 0; c < BATCH; c++) aC[c] = aN[c];
    }
#undef PAIR_AT

    // Merge even/odd parity top-8 (both sorted desc): bitonic top-8 of union
    float other[KTOP];
#pragma unroll
    for (int j = 0; j < KTOP; j++)
        other[j] = __shfl_xor_sync(0xffffffffu, arr[j], 16);
    float L[KTOP];
#pragma unroll
    for (int j = 0; j < KTOP; j++)
        L[j] = fmaxf(arr[j], other[KTOP - 1 - j]);
    // half-cleaner sort (desc) of bitonic sequence, length 8
    CE(L[0], L[4]); CE(L[1], L[5]); CE(L[2], L[6]); CE(L[3], L[7]);
    CE(L[0], L[2]); CE(L[1], L[3]); CE(L[4], L[6]); CE(L[5], L[7]);
    CE(L[0], L[1]); CE(L[2], L[3]); CE(L[4], L[5]); CE(L[6], L[7]);

    if (sub == 0) {
        float* o = out + (size_t)m * OUT_ROW + FF + f;
#pragma unroll
        for (int j = 0; j < KTOP; j++) o[j * FF] = L[j];
        out[(size_t)m * OUT_ROW + f] = __ldg(&x[m * FF + f]);
    }
}

extern "C" void kernel_launch(void* const* d_in, const int* in_sizes, int n_in,
                              void* d_out, int out_size) {
    const float* x   = (const float*)d_in[0];
    const float* adj = (const float*)d_in[1];
    if (in_sizes[0] == NN * NN) {
        adj = (const float*)d_in[0];
        x   = (const float*)d_in[1];
    }
    float* out = (float*)d_out;

    dim3 tgrid(NN / 32, FF / 32);
    transpose_kernel<<<tgrid, dim3(32, 8)>>>(x);
    bin_cols_kernel<<<FF, 512>>>();

    // 64 f * 128 m-groups = 8192 warps -> 2048 blocks of 128 threads
    topk_scan_kernel<<<2048, 128>>>(adj, x, out);
}